// round 6
// baseline (speedup 1.0000x reference)
#include <cuda_runtime.h>
#include <cuda_pipeline.h>

#define B_ 2
#define T_ 192
#define NH 8
#define DH 64
#define DM 512

typedef unsigned long long u64;

// ---------------- f32x2 helpers (used ONLY in k_step1, where they won) -----
__device__ __forceinline__ void fma2(u64 &d, u64 a, u64 b){
  asm("fma.rn.f32x2 %0, %1, %2, %0;" : "+l"(d) : "l"(a), "l"(b));
}
__device__ __forceinline__ u64 pack2(float lo, float hi){
  u64 d; asm("mov.b64 %0, {%1, %2};" : "=l"(d)
             : "r"(__float_as_uint(lo)), "r"(__float_as_uint(hi)));
  return d;
}
__device__ __forceinline__ void unpack2(u64 v, float &lo, float &hi){
  unsigned a, b;
  asm("mov.b64 {%0, %1}, %2;" : "=r"(a), "=r"(b) : "l"(v));
  lo = __uint_as_float(a); hi = __uint_as_float(b);
}

// ---------------- device scratch (static, no allocs) ----------------
__device__ float g_proj[5*B_*NH*T_*DH];      // a,b,c,d,e  [sel][b][n][t][h]
__device__ float g_bsum[B_*T_*DH];           // sum over heads of b-proj
__device__ float g_wkT[NH*DH*4096];          // W_K transposed: [n][k][i*64+j]
__device__ float g_step1[B_*T_*4096];        // [b][r][i*64+j]
__device__ float g_step2[(size_t)B_*T_*T_*DH]; // [b][r][q][i]  (transposed)
__device__ float g_dv[(size_t)B_*NH*T_*DH*DH]; // [b][n][p][g][k]
__device__ float g_z[B_*T_*NH*DH];           // [b][r][n][k]

__device__ __forceinline__ int proj_off(int sel,int b,int n,int t,int h){
  return (((sel*B_+b)*NH+n)*T_+t)*DH+h;
}

// ---------------- projections a..e ----------------
__global__ __launch_bounds__(256) void k_proj(
  const float* __restrict__ x,
  const float* __restrict__ wA, const float* __restrict__ wB,
  const float* __restrict__ wC, const float* __restrict__ wD,
  const float* __restrict__ wE,
  const float* __restrict__ bA, const float* __restrict__ bB,
  const float* __restrict__ bC, const float* __restrict__ bD,
  const float* __restrict__ bE)
{
  int sel = blockIdx.y >> 3, n = blockIdx.y & 7;
  int tok0 = blockIdx.x * 8;
  int b = tok0 / T_, t0 = tok0 % T_;
  const float* W; const float* bias;
  switch(sel){
    case 0: W=wA; bias=bA; break;
    case 1: W=wB; bias=bB; break;
    case 2: W=wC; bias=bC; break;
    case 3: W=wD; bias=bD; break;
    default: W=wE; bias=bE; break;
  }
  W += n*DM*DH; bias += n*DH;
  __shared__ float xs[8][DM];
  __shared__ float wsm[64][DH];
  int tid = threadIdx.x;
  for (int idx=tid; idx<8*DM; idx+=256)
    xs[idx>>9][idx&511] = x[(tok0 + (idx>>9))*DM + (idx&511)];
  int h = tid & 63, tg = tid >> 6;
  float acc0=0.f, acc1=0.f;
  for (int dd0=0; dd0<DM; dd0+=64){
    __syncthreads();
    for (int idx=tid; idx<64*DH; idx+=256)
      wsm[idx>>6][idx&63] = W[(dd0+(idx>>6))*DH + (idx&63)];
    __syncthreads();
    #pragma unroll 16
    for (int dd=0; dd<64; dd++){
      float wv = wsm[dd][h];
      acc0 += xs[2*tg  ][dd0+dd]*wv;
      acc1 += xs[2*tg+1][dd0+dd]*wv;
    }
  }
  float bv = bias[h];
  g_proj[proj_off(sel,b,n,t0+2*tg  ,h)] = acc0+bv;
  g_proj[proj_off(sel,b,n,t0+2*tg+1,h)] = acc1+bv;
}

// ---------------- bsum over heads ----------------
__global__ void k_bsum(){
  int idx = blockIdx.x*256 + threadIdx.x;
  if (idx >= B_*T_*DH) return;
  int b = idx / (T_*DH); int qj = idx % (T_*DH);
  float s = 0.f;
  #pragma unroll
  for (int n=0;n<NH;n++) s += g_proj[((1*B_+b)*NH+n)*T_*DH + qj];
  g_bsum[idx] = s;
}

// ---------------- W_K transpose to [n][k][ij] ----------------
__global__ void k_wkT(const float* __restrict__ WK){
  int o = blockIdx.x*256 + threadIdx.x;
  if (o >= NH*DH*4096) return;
  int n = o >> 18; int rem = o & 262143;
  int k = rem >> 12; int ij = rem & 4095;
  int i = ij >> 6, j = ij & 63;
  g_wkT[o] = WK[((n*64+i)*64+j)*64 + k];
}

// ---------------- step1 (R5 version — measured 89.7us, keep) ----------------
__global__ __launch_bounds__(256) void k_step1(){
  int tok0 = blockIdx.x*16; int b = tok0/T_, t0 = tok0%T_;
  int col0 = blockIdx.y*256;
  extern __shared__ float s1sm[];
  float* cT  = s1sm;           // [512 nk][16 t]
  float* ws0 = s1sm + 8192;
  float* ws1 = s1sm + 16384;
  int tid = threadIdx.x;
  for (int idx=tid; idx<8192; idx+=256){
    int t = idx>>9, nk = idx&511;
    int nn = nk>>6, k = nk&63;
    cT[nk*16 + t] = g_proj[proj_off(2,b,nn,t0+t,k)];
  }
  {
    const float* src = g_wkT + col0;
    #pragma unroll
    for (int j=0;j<8;j++){
      int e = tid + j*256;
      int row = e>>6, c4 = e&63;
      __pipeline_memcpy_async(ws0 + row*256 + c4*4, src + (size_t)row*4096 + c4*4, 16);
    }
    __pipeline_commit();
  }
  int colq = tid & 63, tg = tid >> 6;
  u64 acc[4][2];
  #pragma unroll
  for (int i=0;i<4;i++){ acc[i][0]=0ull; acc[i][1]=0ull; }
  for (int nkc=0; nkc<16; nkc++){
    float* cur = (nkc&1) ? ws1 : ws0;
    float* nxt = (nkc&1) ? ws0 : ws1;
    __pipeline_wait_prior(0);
    __syncthreads();
    if (nkc < 15){
      const float* src = g_wkT + ((size_t)(nkc+1)*32)*4096 + col0;
      #pragma unroll
      for (int j=0;j<8;j++){
        int e = tid + j*256;
        int row = e>>6, c4 = e&63;
        __pipeline_memcpy_async(nxt + row*256 + c4*4, src + (size_t)row*4096 + c4*4, 16);
      }
      __pipeline_commit();
    }
    #pragma unroll 8
    for (int nk=0; nk<32; nk++){
      float4 cv = *(const float4*)&cT[(nkc*32+nk)*16 + 4*tg];
      ulonglong2 wv = *(const ulonglong2*)&cur[nk*256 + 4*colq];
      u64 c0 = pack2(cv.x,cv.x), c1 = pack2(cv.y,cv.y);
      u64 c2 = pack2(cv.z,cv.z), c3 = pack2(cv.w,cv.w);
      fma2(acc[0][0], c0, wv.x); fma2(acc[0][1], c0, wv.y);
      fma2(acc[1][0], c1, wv.x); fma2(acc[1][1], c1, wv.y);
      fma2(acc[2][0], c2, wv.x); fma2(acc[2][1], c2, wv.y);
      fma2(acc[3][0], c3, wv.x); fma2(acc[3][1], c3, wv.y);
    }
  }
  #pragma unroll
  for (int i=0;i<4;i++){
    float v0,v1,v2,v3;
    unpack2(acc[i][0], v0, v1);
    unpack2(acc[i][1], v2, v3);
    float* dst = g_step1 + (size_t)(b*T_+t0+4*tg+i)*4096 + col0 + 4*colq;
    *(float4*)dst = make_float4(v0,v1,v2,v3);
  }
}

// ---------------- step2[b,r,q,i] (transposed output, R5 version) ------------
__global__ __launch_bounds__(256) void k_step2(){
  int rowtile = blockIdx.x;           // 0..383
  int r = rowtile >> 1, i0 = (rowtile & 1)*32;
  int b = blockIdx.y;
  extern __shared__ float s2sm[];
  float* s1s = s2sm;                  // [32][64]
  float* bsm = s2sm + 2048;           // [192][65] padded
  int tid = threadIdx.x;
  const float* s1src = g_step1 + (b*T_+r)*4096 + i0*64;
  for (int idx=tid; idx<2048; idx+=256) s1s[idx] = s1src[idx];
  for (int idx=tid; idx<T_*64; idx+=256){
    int q = idx>>6, j = idx&63;
    bsm[q*65+j] = g_bsum[b*T_*64 + idx];
  }
  __syncthreads();
  int q0 = tid & 31, ir = tid >> 5;
  float acc[4][6];
  #pragma unroll
  for (int a1=0;a1<4;a1++){
    #pragma unroll
    for(int m=0;m<6;m++) acc[a1][m]=0.f; }
  for (int j=0;j<64;j++){
    float s1v[4];
    #pragma unroll
    for (int rr=0;rr<4;rr++) s1v[rr] = s1s[(ir*4+rr)*64 + j];
    float bv[6];
    #pragma unroll
    for (int m=0;m<6;m++) bv[m] = bsm[(q0+32*m)*65 + j];
    #pragma unroll
    for (int rr=0;rr<4;rr++)
      #pragma unroll
      for (int m=0;m<6;m++)
        acc[rr][m] += s1v[rr]*bv[m];
  }
  #pragma unroll
  for (int m=0;m<6;m++){
    int q = q0 + 32*m;
    float* dst = g_step2 + ((size_t)(b*T_+r)*T_ + q)*64 + i0 + ir*4;
    *(float4*)dst = make_float4(acc[0][m],acc[1][m],acc[2][m],acc[3][m]);
  }
}

// ---------------- dv[b,n,p,g,k] = sum_h d * W_V ----------------
__global__ __launch_bounds__(256) void k_dv(const float* __restrict__ WV){
  int p0 = blockIdx.x*4;
  int gh = blockIdx.y;
  int bn = blockIdx.z; int b = bn>>3, n = bn&7;
  __shared__ float ds[4][64];
  int tid = threadIdx.x;
  ds[tid>>6][tid&63] = g_proj[proj_off(3,b,n,p0+(tid>>6),tid&63)];
  __syncthreads();
  int k = tid & 63, g0 = gh*32 + (tid>>6);
  float acc[4][8];
  #pragma unroll
  for(int p=0;p<4;p++){
    #pragma unroll
    for(int g=0;g<8;g++) acc[p][g]=0.f; }
  for (int h=0;h<64;h++){
    float d0=ds[0][h], d1=ds[1][h], d2=ds[2][h], d3=ds[3][h];
    const float* wp = WV + ((n*64+h)*64 + g0)*64 + k;
    #pragma unroll
    for (int gg=0;gg<8;gg++){
      float wv = wp[gg*256];
      acc[0][gg]+=d0*wv; acc[1][gg]+=d1*wv; acc[2][gg]+=d2*wv; acc[3][gg]+=d3*wv;
    }
  }
  for (int pp=0;pp<4;pp++)
    #pragma unroll
    for (int gg=0;gg<8;gg++){
      int g = g0 + 4*gg;
      g_dv[(((size_t)(b*NH+n)*T_ + p0+pp)*64 + g)*64 + k] = acc[pp][gg];
    }
}

// ---------------- main fused kernel: scalar FFMA (R3-proven structure), ------
// but step2 staged [q][i] at stride 68 so S loads are LDS.128 too.
__global__ __launch_bounds__(384) void k_main(){
  int rp = 95 - blockIdx.x;           // heavy CTAs first
  int r0 = rp*2, r1 = r0+1;
  int n = blockIdx.y, b = blockIdx.z;
  int tid = threadIdx.x;
  extern __shared__ float sm[];
  float* s2t0 = sm;                   // 192 x 68 = 13056
  float* s2t1 = sm + 13056;           // 13056
  float* as_  = sm + 26112;           // [p][i] 12288
  float* es_  = sm + 38400;           // [q][g] 12288
  float* pwb  = sm + 50688;           // 12 warps x 512 (P bufs / w rows / z)
  {
    const float4* src0 = (const float4*)(g_step2 + (size_t)(b*T_+r0)*T_*64);
    const float4* src1 = (const float4*)(g_step2 + (size_t)(b*T_+r1)*T_*64);
    for (int idx=tid; idx<3072; idx+=384){
      int q = idx>>4, c = idx&15;
      *(float4*)(s2t0 + q*68 + c*4) = src0[idx];
      *(float4*)(s2t1 + q*68 + c*4) = src1[idx];
    }
    const float4* asrc = (const float4*)(g_proj + proj_off(0,b,n,0,0));
    const float4* esrc = (const float4*)(g_proj + proj_off(4,b,n,0,0));
    for (int idx=tid; idx<3072; idx+=384){
      *(float4*)(as_ + idx*4) = asrc[idx];
      *(float4*)(es_ + idx*4) = esrc[idx];
    }
  }
  __syncthreads();
  int warp = tid >> 5, lane = tid & 31;
  float* pw = pwb + warp*512;
  float4* psw0 = (float4*)pw;         // 32 float4 (P for r0)
  float4* psw1 = (float4*)(pw + 128); // 32 float4 (P for r1)
  float z0x=0.f,z0y=0.f,z1x=0.f,z1y=0.f,l0=0.f,l1=0.f;
  int ntiles = (r1+3)>>2;
  const float* dvbn = g_dv + (size_t)(b*NH+n)*T_*4096;
  const float sc = 0.015625f;
  for (int t = warp; t < ntiles; t += 12){
    int p0 = t*4;
    float w0[8], w1[8];
    #pragma unroll
    for (int j=0;j<8;j++){ w0[j]=0.f; w1[j]=0.f; }
    for (int qc = p0>>5; qc < 6; qc++){
      int q = qc*32 + lane;
      float a00=0.f,a01=0.f,a02=0.f,a03=0.f;
      float a10=0.f,a11=0.f,a12=0.f,a13=0.f;
      const float* ap  = as_ + p0*64;
      const float* s0p = s2t0 + q*68;
      const float* s1p = s2t1 + q*68;
      #pragma unroll
      for (int i=0;i<64;i+=4){
        float4 A0 = *(const float4*)(ap + i);
        float4 A1 = *(const float4*)(ap + 64 + i);
        float4 A2 = *(const float4*)(ap + 128 + i);
        float4 A3 = *(const float4*)(ap + 192 + i);
        float4 S0 = *(const float4*)(s0p + i);
        float4 S1 = *(const float4*)(s1p + i);
        a00+=A0.x*S0.x; a00+=A0.y*S0.y; a00+=A0.z*S0.z; a00+=A0.w*S0.w;
        a01+=A1.x*S0.x; a01+=A1.y*S0.y; a01+=A1.z*S0.z; a01+=A1.w*S0.w;
        a02+=A2.x*S0.x; a02+=A2.y*S0.y; a02+=A2.z*S0.z; a02+=A2.w*S0.w;
        a03+=A3.x*S0.x; a03+=A3.y*S0.y; a03+=A3.z*S0.z; a03+=A3.w*S0.w;
        a10+=A0.x*S1.x; a10+=A0.y*S1.y; a10+=A0.z*S1.z; a10+=A0.w*S1.w;
        a11+=A1.x*S1.x; a11+=A1.y*S1.y; a11+=A1.z*S1.z; a11+=A1.w*S1.w;
        a12+=A2.x*S1.x; a12+=A2.y*S1.y; a12+=A2.z*S1.z; a12+=A2.w*S1.w;
        a13+=A3.x*S1.x; a13+=A3.y*S1.y; a13+=A3.z*S1.z; a13+=A3.w*S1.w;
      }
      float P00 = (p0+0<r0 && q>p0+0) ? __expf(a00*sc) : 0.f;
      float P01 = (p0+1<r0 && q>p0+1) ? __expf(a01*sc) : 0.f;
      float P02 = (p0+2<r0 && q>p0+2) ? __expf(a02*sc) : 0.f;
      float P03 = (p0+3<r0 && q>p0+3) ? __expf(a03*sc) : 0.f;
      float P10 = (p0+0<r1 && q>p0+0) ? __expf(a10*sc) : 0.f;
      float P11 = (p0+1<r1 && q>p0+1) ? __expf(a11*sc) : 0.f;
      float P12 = (p0+2<r1 && q>p0+2) ? __expf(a12*sc) : 0.f;
      float P13 = (p0+3<r1 && q>p0+3) ? __expf(a13*sc) : 0.f;
      l0 += P00+P01+P02+P03;
      l1 += P10+P11+P12+P13;
      psw0[lane] = make_float4(P00,P01,P02,P03);
      psw1[lane] = make_float4(P10,P11,P12,P13);
      __syncwarp();
      const float* eb = es_ + qc*2048;
      #pragma unroll 8
      for (int qq=0; qq<32; qq++){
        float e0 = eb[qq*64 + lane];
        float e1 = eb[qq*64 + lane + 32];
        float4 Pa = psw0[qq];
        float4 Pb = psw1[qq];
        w0[0]+=Pa.x*e0; w0[1]+=Pa.x*e1;
        w0[2]+=Pa.y*e0; w0[3]+=Pa.y*e1;
        w0[4]+=Pa.z*e0; w0[5]+=Pa.z*e1;
        w0[6]+=Pa.w*e0; w0[7]+=Pa.w*e1;
        w1[0]+=Pb.x*e0; w1[1]+=Pb.x*e1;
        w1[2]+=Pb.y*e0; w1[3]+=Pb.y*e1;
        w1[4]+=Pb.z*e0; w1[5]+=Pb.z*e1;
        w1[6]+=Pb.w*e0; w1[7]+=Pb.w*e1;
      }
      __syncwarp();
    }
    // dump w rows to warp-private smem (reuses P buffers; P is dead)
    __syncwarp();
    #pragma unroll
    for (int pp=0;pp<4;pp++){
      pw[pp*128 + lane     ] = w0[2*pp];
      pw[pp*128 + lane + 32] = w0[2*pp+1];
      pw[pp*128 + lane + 64] = w1[2*pp];
      pw[pp*128 + lane + 96] = w1[2*pp+1];
    }
    __syncwarp();
    int pmax = min(4, r1 - p0);
    for (int pp=0; pp<pmax; pp++){
      const float* dvp = dvbn + (size_t)(p0+pp)*4096 + 2*lane;
      const float* w0r = pw + pp*128;
      const float* w1r = w0r + 64;
      #pragma unroll 8
      for (int g=0; g<64; g++){
        float2 d2 = *(const float2*)(dvp + g*64);
        float wv0 = w0r[g], wv1 = w1r[g];
        z0x += wv0*d2.x; z0y += wv0*d2.y;
        z1x += wv1*d2.x; z1y += wv1*d2.y;
      }
    }
    __syncwarp();
  }
  // per-warp z partials + l into own slot (pw is dead now)
  pw[2*lane    ] = z0x; pw[2*lane + 1 ] = z0y;
  pw[64+2*lane ] = z1x; pw[64+2*lane+1] = z1y;
  #pragma unroll
  for (int off=16; off>0; off>>=1){
    l0 += __shfl_xor_sync(0xffffffffu, l0, off);
    l1 += __shfl_xor_sync(0xffffffffu, l1, off);
  }
  if (lane==0){ pw[128]=l0; pw[129]=l1; }
  __syncthreads();
  if (tid < 128){
    int rr = tid >> 6, k = tid & 63;
    float zs=0.f, lt=0.f;
    #pragma unroll
    for (int w=0; w<12; w++){
      zs += pwb[w*512 + rr*64 + k];
      lt += pwb[w*512 + 128 + rr];
    }
    int r = r0 + rr;
    g_z[((b*T_+r)*NH+n)*DH + k] = (r==0) ? 0.f : zs/lt;
  }
}

// ---------------- output projection ----------------
__global__ __launch_bounds__(256) void k_out(const float* __restrict__ WO,
                                             const float* __restrict__ bO,
                                             float* __restrict__ out){
  int tok0 = blockIdx.x*4;
  __shared__ float zs[4][512];
  int tid = threadIdx.x;
  for (int idx=tid; idx<4*512; idx+=256)
    zs[idx>>9][idx&511] = g_z[(tok0+(idx>>9))*512 + (idx&511)];
  __syncthreads();
  float acc[4][2];
  #pragma unroll
  for(int t=0;t<4;t++){acc[t][0]=0.f;acc[t][1]=0.f;}
  for (int nh=0; nh<512; nh++){
    float w0 = WO[nh*512 + tid      ];
    float w1 = WO[nh*512 + tid + 256];
    #pragma unroll
    for (int t=0;t<4;t++){
      float zv = zs[t][nh];
      acc[t][0] += zv*w0; acc[t][1] += zv*w1;
    }
  }
  float b0 = bO[tid], b1 = bO[tid+256];
  for (int t=0;t<4;t++){
    out[(tok0+t)*512 + tid      ] = acc[t][0] + b0;
    out[(tok0+t)*512 + tid + 256] = acc[t][1] + b1;
  }
}

// ---------------- launch ----------------
extern "C" void kernel_launch(void* const* d_in, const int* in_sizes, int n_in,
                              void* d_out, int out_size){
  const float* x  = (const float*)d_in[0];
  const float* wA = (const float*)d_in[1];
  const float* wB = (const float*)d_in[2];
  const float* wC = (const float*)d_in[3];
  const float* wD = (const float*)d_in[4];
  const float* wE = (const float*)d_in[5];
  const float* WK = (const float*)d_in[6];
  const float* WV = (const float*)d_in[7];
  const float* WO = (const float*)d_in[8];
  const float* bA = (const float*)d_in[9];
  const float* bB = (const float*)d_in[10];
  const float* bC = (const float*)d_in[11];
  const float* bD = (const float*)d_in[12];
  const float* bE = (const float*)d_in[13];
  const float* bO = (const float*)d_in[14];
  float* out = (float*)d_out;

  k_proj<<<dim3(48,40),256>>>(x,wA,wB,wC,wD,wE,bA,bB,bC,bD,bE);
  k_bsum<<<(B_*T_*DH+255)/256,256>>>();
  k_wkT<<<(NH*DH*4096+255)/256,256>>>(WK);
  size_t s1smem = 24576*sizeof(float);            // 96KB
  cudaFuncSetAttribute(k_step1, cudaFuncAttributeMaxDynamicSharedMemorySize, (int)s1smem);
  k_step1<<<dim3(24,16),256,s1smem>>>();
  size_t s2smem = (2048 + 192*65)*sizeof(float);
  cudaFuncSetAttribute(k_step2, cudaFuncAttributeMaxDynamicSharedMemorySize, (int)s2smem);
  k_step2<<<dim3(384,2),256,s2smem>>>();
  k_dv<<<dim3(48,2,16),256>>>(WV);
  size_t msmem = 56832*sizeof(float);             // 227328 B
  cudaFuncSetAttribute(k_main, cudaFuncAttributeMaxDynamicSharedMemorySize, (int)msmem);
  k_main<<<dim3(96,NH,B_),384,msmem>>>();
  k_out<<<96,256>>>(WO,bO,out);
}

// round 8
// speedup vs baseline: 1.4627x; 1.4627x over previous
#include <cuda_runtime.h>
#include <cuda_pipeline.h>

#define B_ 2
#define T_ 192
#define NH 8
#define DH 64
#define DM 512

typedef unsigned long long u64;

// ---------------- f32x2 helpers (used ONLY in k_step1, where they won) -----
__device__ __forceinline__ void fma2(u64 &d, u64 a, u64 b){
  asm("fma.rn.f32x2 %0, %1, %2, %0;" : "+l"(d) : "l"(a), "l"(b));
}
__device__ __forceinline__ u64 pack2(float lo, float hi){
  u64 d; asm("mov.b64 %0, {%1, %2};" : "=l"(d)
             : "r"(__float_as_uint(lo)), "r"(__float_as_uint(hi)));
  return d;
}
__device__ __forceinline__ void unpack2(u64 v, float &lo, float &hi){
  unsigned a, b;
  asm("mov.b64 {%0, %1}, %2;" : "=r"(a), "=r"(b) : "l"(v));
  lo = __uint_as_float(a); hi = __uint_as_float(b);
}

// ---------------- device scratch (static, no allocs) ----------------
__device__ float g_proj[5*B_*NH*T_*DH];      // a,b,c,d,e  [sel][b][n][t][h]
__device__ float g_bsum[B_*T_*DH];           // sum over heads of b-proj
__device__ float g_wkT[NH*DH*4096];          // W_K transposed: [n][k][i*64+j]
__device__ float g_step1[B_*T_*4096];        // [b][r][i*64+j]
__device__ float g_step2[(size_t)B_*T_*DH*T_]; // [b][r][i][q]  (R3 layout)
__device__ float g_dv[(size_t)B_*NH*T_*DH*DH]; // [b][n][p][g][k]
__device__ float g_z[B_*T_*NH*DH];           // [b][r][n][k]

__device__ __forceinline__ int proj_off(int sel,int b,int n,int t,int h){
  return (((sel*B_+b)*NH+n)*T_+t)*DH+h;
}

// ---------------- projections a..e ----------------
__global__ __launch_bounds__(256) void k_proj(
  const float* __restrict__ x,
  const float* __restrict__ wA, const float* __restrict__ wB,
  const float* __restrict__ wC, const float* __restrict__ wD,
  const float* __restrict__ wE,
  const float* __restrict__ bA, const float* __restrict__ bB,
  const float* __restrict__ bC, const float* __restrict__ bD,
  const float* __restrict__ bE)
{
  int sel = blockIdx.y >> 3, n = blockIdx.y & 7;
  int tok0 = blockIdx.x * 8;
  int b = tok0 / T_, t0 = tok0 % T_;
  const float* W; const float* bias;
  switch(sel){
    case 0: W=wA; bias=bA; break;
    case 1: W=wB; bias=bB; break;
    case 2: W=wC; bias=bC; break;
    case 3: W=wD; bias=bD; break;
    default: W=wE; bias=bE; break;
  }
  W += n*DM*DH; bias += n*DH;
  __shared__ float xs[8][DM];
  __shared__ float wsm[64][DH];
  int tid = threadIdx.x;
  for (int idx=tid; idx<8*DM; idx+=256)
    xs[idx>>9][idx&511] = x[(tok0 + (idx>>9))*DM + (idx&511)];
  int h = tid & 63, tg = tid >> 6;
  float acc0=0.f, acc1=0.f;
  for (int dd0=0; dd0<DM; dd0+=64){
    __syncthreads();
    for (int idx=tid; idx<64*DH; idx+=256)
      wsm[idx>>6][idx&63] = W[(dd0+(idx>>6))*DH + (idx&63)];
    __syncthreads();
    #pragma unroll 16
    for (int dd=0; dd<64; dd++){
      float wv = wsm[dd][h];
      acc0 += xs[2*tg  ][dd0+dd]*wv;
      acc1 += xs[2*tg+1][dd0+dd]*wv;
    }
  }
  float bv = bias[h];
  g_proj[proj_off(sel,b,n,t0+2*tg  ,h)] = acc0+bv;
  g_proj[proj_off(sel,b,n,t0+2*tg+1,h)] = acc1+bv;
}

// ---------------- bsum over heads ----------------
__global__ void k_bsum(){
  int idx = blockIdx.x*256 + threadIdx.x;
  if (idx >= B_*T_*DH) return;
  int b = idx / (T_*DH); int qj = idx % (T_*DH);
  float s = 0.f;
  #pragma unroll
  for (int n=0;n<NH;n++) s += g_proj[((1*B_+b)*NH+n)*T_*DH + qj];
  g_bsum[idx] = s;
}

// ---------------- W_K transpose to [n][k][ij] ----------------
__global__ void k_wkT(const float* __restrict__ WK){
  int o = blockIdx.x*256 + threadIdx.x;
  if (o >= NH*DH*4096) return;
  int n = o >> 18; int rem = o & 262143;
  int k = rem >> 12; int ij = rem & 4095;
  int i = ij >> 6, j = ij & 63;
  g_wkT[o] = WK[((n*64+i)*64+j)*64 + k];
}

// ---------------- step1 (R5 version — measured 88.8us, proven) --------------
__global__ __launch_bounds__(256) void k_step1(){
  int tok0 = blockIdx.x*16; int b = tok0/T_, t0 = tok0%T_;
  int col0 = blockIdx.y*256;
  extern __shared__ float s1sm[];
  float* cT  = s1sm;           // [512 nk][16 t]
  float* ws0 = s1sm + 8192;
  float* ws1 = s1sm + 16384;
  int tid = threadIdx.x;
  for (int idx=tid; idx<8192; idx+=256){
    int t = idx>>9, nk = idx&511;
    int nn = nk>>6, k = nk&63;
    cT[nk*16 + t] = g_proj[proj_off(2,b,nn,t0+t,k)];
  }
  {
    const float* src = g_wkT + col0;
    #pragma unroll
    for (int j=0;j<8;j++){
      int e = tid + j*256;
      int row = e>>6, c4 = e&63;
      __pipeline_memcpy_async(ws0 + row*256 + c4*4, src + (size_t)row*4096 + c4*4, 16);
    }
    __pipeline_commit();
  }
  int colq = tid & 63, tg = tid >> 6;
  u64 acc[4][2];
  #pragma unroll
  for (int i=0;i<4;i++){ acc[i][0]=0ull; acc[i][1]=0ull; }
  for (int nkc=0; nkc<16; nkc++){
    float* cur = (nkc&1) ? ws1 : ws0;
    float* nxt = (nkc&1) ? ws0 : ws1;
    __pipeline_wait_prior(0);
    __syncthreads();
    if (nkc < 15){
      const float* src = g_wkT + ((size_t)(nkc+1)*32)*4096 + col0;
      #pragma unroll
      for (int j=0;j<8;j++){
        int e = tid + j*256;
        int row = e>>6, c4 = e&63;
        __pipeline_memcpy_async(nxt + row*256 + c4*4, src + (size_t)row*4096 + c4*4, 16);
      }
      __pipeline_commit();
    }
    #pragma unroll 8
    for (int nk=0; nk<32; nk++){
      float4 cv = *(const float4*)&cT[(nkc*32+nk)*16 + 4*tg];
      ulonglong2 wv = *(const ulonglong2*)&cur[nk*256 + 4*colq];
      u64 c0 = pack2(cv.x,cv.x), c1 = pack2(cv.y,cv.y);
      u64 c2 = pack2(cv.z,cv.z), c3 = pack2(cv.w,cv.w);
      fma2(acc[0][0], c0, wv.x); fma2(acc[0][1], c0, wv.y);
      fma2(acc[1][0], c1, wv.x); fma2(acc[1][1], c1, wv.y);
      fma2(acc[2][0], c2, wv.x); fma2(acc[2][1], c2, wv.y);
      fma2(acc[3][0], c3, wv.x); fma2(acc[3][1], c3, wv.y);
    }
  }
  #pragma unroll
  for (int i=0;i<4;i++){
    float v0,v1,v2,v3;
    unpack2(acc[i][0], v0, v1);
    unpack2(acc[i][1], v2, v3);
    float* dst = g_step1 + (size_t)(b*T_+t0+4*tg+i)*4096 + col0 + 4*colq;
    *(float4*)dst = make_float4(v0,v1,v2,v3);
  }
}

// ---------------- step2[b,r,i,q] (R3 layout — proven with this k_main) ------
__global__ __launch_bounds__(256) void k_step2(){
  int rowtile = blockIdx.x;           // 0..383
  int r = rowtile >> 1, i0 = (rowtile & 1)*32;
  int b = blockIdx.y;
  extern __shared__ float s2sm[];
  float* s1s = s2sm;                  // [32][64]
  float* bsm = s2sm + 2048;           // [192][65] padded
  int tid = threadIdx.x;
  const float* s1src = g_step1 + (b*T_+r)*4096 + i0*64;
  for (int idx=tid; idx<2048; idx+=256) s1s[idx] = s1src[idx];
  for (int idx=tid; idx<T_*64; idx+=256){
    int q = idx>>6, j = idx&63;
    bsm[q*65+j] = g_bsum[b*T_*64 + idx];
  }
  __syncthreads();
  int q0 = tid & 31, ir = tid >> 5;
  float acc[4][6];
  #pragma unroll
  for (int a1=0;a1<4;a1++){
    #pragma unroll
    for(int m=0;m<6;m++) acc[a1][m]=0.f; }
  for (int j=0;j<64;j++){
    float s1v[4];
    #pragma unroll
    for (int rr=0;rr<4;rr++) s1v[rr] = s1s[(ir*4+rr)*64 + j];
    float bv[6];
    #pragma unroll
    for (int m=0;m<6;m++) bv[m] = bsm[(q0+32*m)*65 + j];
    #pragma unroll
    for (int rr=0;rr<4;rr++)
      #pragma unroll
      for (int m=0;m<6;m++)
        acc[rr][m] += s1v[rr]*bv[m];
  }
  for (int rr=0;rr<4;rr++){
    int iloc = i0 + ir*4 + rr;
    float* dst = g_step2 + ((size_t)(b*T_+r)*64 + iloc)*T_;
    #pragma unroll
    for (int m=0;m<6;m++) dst[q0+32*m] = acc[rr][m];
  }
}

// ---------------- dv[b,n,p,g,k] = sum_h d * W_V ----------------
__global__ __launch_bounds__(256) void k_dv(const float* __restrict__ WV){
  int p0 = blockIdx.x*4;
  int gh = blockIdx.y;
  int bn = blockIdx.z; int b = bn>>3, n = bn&7;
  __shared__ float ds[4][64];
  int tid = threadIdx.x;
  ds[tid>>6][tid&63] = g_proj[proj_off(3,b,n,p0+(tid>>6),tid&63)];
  __syncthreads();
  int k = tid & 63, g0 = gh*32 + (tid>>6);
  float acc[4][8];
  #pragma unroll
  for(int p=0;p<4;p++){
    #pragma unroll
    for(int g=0;g<8;g++) acc[p][g]=0.f; }
  for (int h=0;h<64;h++){
    float d0=ds[0][h], d1=ds[1][h], d2=ds[2][h], d3=ds[3][h];
    const float* wp = WV + ((n*64+h)*64 + g0)*64 + k;
    #pragma unroll
    for (int gg=0;gg<8;gg++){
      float wv = wp[gg*256];
      acc[0][gg]+=d0*wv; acc[1][gg]+=d1*wv; acc[2][gg]+=d2*wv; acc[3][gg]+=d3*wv;
    }
  }
  for (int pp=0;pp<4;pp++)
    #pragma unroll
    for (int gg=0;gg<8;gg++){
      int g = g0 + 4*gg;
      g_dv[(((size_t)(b*NH+n)*T_ + p0+pp)*64 + g)*64 + k] = acc[pp][gg];
    }
}

// ---------------- main fused scores/softmax/z kernel (R3 version, proven) ---
__global__ __launch_bounds__(384) void k_main(){
  int rp = 95 - blockIdx.x;           // heavy CTAs first
  int r0 = rp*2, r1 = r0+1;
  int n = blockIdx.y, b = blockIdx.z;
  int tid = threadIdx.x;
  extern __shared__ float sm[];
  float* s20 = sm;                    // 12288 : step2[r0][i][q]
  float* s21 = sm + 12288;            // 12288 : step2[r1][i][q]
  float* as_ = sm + 24576;            // 12288 : a[p][i]
  float* es_ = sm + 36864;            // 12288 : e[q][g]
  float* pwb = sm + 49152;            // 12 warps x 512 (P bufs / w rows, reused)
  float* zpt = sm + 55296;            // 12 x 128
  float* lpt = sm + 56832;            // 24
  const float* s2src0 = g_step2 + (size_t)(b*T_+r0)*64*T_;
  const float* s2src1 = g_step2 + (size_t)(b*T_+r1)*64*T_;
  for (int idx=tid; idx<12288; idx+=384){ s20[idx]=s2src0[idx]; s21[idx]=s2src1[idx]; }
  const float* asrc = g_proj + proj_off(0,b,n,0,0);
  const float* esrc = g_proj + proj_off(4,b,n,0,0);
  for (int idx=tid; idx<12288; idx+=384){ as_[idx]=asrc[idx]; es_[idx]=esrc[idx]; }
  __syncthreads();
  int warp = tid >> 5, lane = tid & 31;
  float* pw = pwb + warp*512;
  float4* psw0 = (float4*)pw;         // 32 float4 (P for r0)
  float4* psw1 = (float4*)(pw + 128); // 32 float4 (P for r1)
  float z0x=0.f,z0y=0.f,z1x=0.f,z1y=0.f,l0=0.f,l1=0.f;
  int ntiles = (r1+3)>>2;
  const float* dvbn = g_dv + (size_t)(b*NH+n)*T_*4096;
  const float sc = 0.015625f;
  for (int t = warp; t < ntiles; t += 12){
    int p0 = t*4;
    float w0[8], w1[8];
    #pragma unroll
    for (int j=0;j<8;j++){ w0[j]=0.f; w1[j]=0.f; }
    for (int qc = p0>>5; qc < 6; qc++){
      int q = qc*32 + lane;
      float a00=0.f,a01=0.f,a02=0.f,a03=0.f;
      float a10=0.f,a11=0.f,a12=0.f,a13=0.f;
      const float* ap  = as_ + p0*64;
      const float* q0p = s20 + q;
      const float* q1p = s21 + q;
      #pragma unroll
      for (int i=0;i<64;i+=4){
        float4 A0 = *(const float4*)(ap + i);
        float4 A1 = *(const float4*)(ap + 64 + i);
        float4 A2 = *(const float4*)(ap + 128 + i);
        float4 A3 = *(const float4*)(ap + 192 + i);
        float s0a=q0p[(i)*192], s0b=q0p[(i+1)*192], s0c=q0p[(i+2)*192], s0d=q0p[(i+3)*192];
        float s1a=q1p[(i)*192], s1b=q1p[(i+1)*192], s1c=q1p[(i+2)*192], s1d=q1p[(i+3)*192];
        a00+=A0.x*s0a; a00+=A0.y*s0b; a00+=A0.z*s0c; a00+=A0.w*s0d;
        a01+=A1.x*s0a; a01+=A1.y*s0b; a01+=A1.z*s0c; a01+=A1.w*s0d;
        a02+=A2.x*s0a; a02+=A2.y*s0b; a02+=A2.z*s0c; a02+=A2.w*s0d;
        a03+=A3.x*s0a; a03+=A3.y*s0b; a03+=A3.z*s0c; a03+=A3.w*s0d;
        a10+=A0.x*s1a; a10+=A0.y*s1b; a10+=A0.z*s1c; a10+=A0.w*s1d;
        a11+=A1.x*s1a; a11+=A1.y*s1b; a11+=A1.z*s1c; a11+=A1.w*s1d;
        a12+=A2.x*s1a; a12+=A2.y*s1b; a12+=A2.z*s1c; a12+=A2.w*s1d;
        a13+=A3.x*s1a; a13+=A3.y*s1b; a13+=A3.z*s1c; a13+=A3.w*s1d;
      }
      float P00 = (p0+0<r0 && q>p0+0) ? __expf(a00*sc) : 0.f;
      float P01 = (p0+1<r0 && q>p0+1) ? __expf(a01*sc) : 0.f;
      float P02 = (p0+2<r0 && q>p0+2) ? __expf(a02*sc) : 0.f;
      float P03 = (p0+3<r0 && q>p0+3) ? __expf(a03*sc) : 0.f;
      float P10 = (p0+0<r1 && q>p0+0) ? __expf(a10*sc) : 0.f;
      float P11 = (p0+1<r1 && q>p0+1) ? __expf(a11*sc) : 0.f;
      float P12 = (p0+2<r1 && q>p0+2) ? __expf(a12*sc) : 0.f;
      float P13 = (p0+3<r1 && q>p0+3) ? __expf(a13*sc) : 0.f;
      l0 += P00+P01+P02+P03;
      l1 += P10+P11+P12+P13;
      psw0[lane] = make_float4(P00,P01,P02,P03);
      psw1[lane] = make_float4(P10,P11,P12,P13);
      __syncwarp();
      const float* eb = es_ + qc*2048;
      #pragma unroll 8
      for (int qq=0; qq<32; qq++){
        float e0 = eb[qq*64 + lane];
        float e1 = eb[qq*64 + lane + 32];
        float4 Pa = psw0[qq];
        float4 Pb = psw1[qq];
        w0[0]+=Pa.x*e0; w0[1]+=Pa.x*e1;
        w0[2]+=Pa.y*e0; w0[3]+=Pa.y*e1;
        w0[4]+=Pa.z*e0; w0[5]+=Pa.z*e1;
        w0[6]+=Pa.w*e0; w0[7]+=Pa.w*e1;
        w1[0]+=Pb.x*e0; w1[1]+=Pb.x*e1;
        w1[2]+=Pb.y*e0; w1[3]+=Pb.y*e1;
        w1[4]+=Pb.z*e0; w1[5]+=Pb.z*e1;
        w1[6]+=Pb.w*e0; w1[7]+=Pb.w*e1;
      }
      __syncwarp();
    }
    // dump w rows to per-warp smem (reuses P buffers; warp-private)
    __syncwarp();
    #pragma unroll
    for (int pp=0;pp<4;pp++){
      pw[pp*128 + lane     ] = w0[2*pp];
      pw[pp*128 + lane + 32] = w0[2*pp+1];
      pw[pp*128 + lane + 64] = w1[2*pp];
      pw[pp*128 + lane + 96] = w1[2*pp+1];
    }
    __syncwarp();
    int pmax = min(4, r1 - p0);
    for (int pp=0; pp<pmax; pp++){
      const float* dvp = dvbn + (size_t)(p0+pp)*4096 + 2*lane;
      const float* w0r = pw + pp*128;
      const float* w1r = w0r + 64;
      #pragma unroll 8
      for (int g=0; g<64; g++){
        float2 d2 = *(const float2*)(dvp + g*64);
        float wv0 = w0r[g], wv1 = w1r[g];
        z0x += wv0*d2.x; z0y += wv0*d2.y;
        z1x += wv1*d2.x; z1y += wv1*d2.y;
      }
    }
    __syncwarp();
  }
  zpt[warp*128 + 2*lane    ] = z0x;
  zpt[warp*128 + 2*lane + 1] = z0y;
  zpt[warp*128 + 2*lane + 64] = z1x;
  zpt[warp*128 + 2*lane + 65] = z1y;
  #pragma unroll
  for (int off=16; off>0; off>>=1){
    l0 += __shfl_xor_sync(0xffffffffu, l0, off);
    l1 += __shfl_xor_sync(0xffffffffu, l1, off);
  }
  if (lane==0){ lpt[warp*2]=l0; lpt[warp*2+1]=l1; }
  __syncthreads();
  if (tid < 128){
    int rr = tid >> 6, k = tid & 63;
    float zs=0.f, lt=0.f;
    #pragma unroll
    for (int w=0; w<12; w++){ zs += zpt[w*128 + rr*64 + k]; lt += lpt[w*2+rr]; }
    int r = r0 + rr;
    g_z[((b*T_+r)*NH+n)*DH + k] = (r==0) ? 0.f : zs/lt;
  }
}

// ---------------- output projection ----------------
__global__ __launch_bounds__(256) void k_out(const float* __restrict__ WO,
                                             const float* __restrict__ bO,
                                             float* __restrict__ out){
  int tok0 = blockIdx.x*4;
  __shared__ float zs[4][512];
  int tid = threadIdx.x;
  for (int idx=tid; idx<4*512; idx+=256)
    zs[idx>>9][idx&511] = g_z[(tok0+(idx>>9))*512 + (idx&511)];
  __syncthreads();
  float acc[4][2];
  #pragma unroll
  for(int t=0;t<4;t++){acc[t][0]=0.f;acc[t][1]=0.f;}
  for (int nh=0; nh<512; nh++){
    float w0 = WO[nh*512 + tid      ];
    float w1 = WO[nh*512 + tid + 256];
    #pragma unroll
    for (int t=0;t<4;t++){
      float zv = zs[t][nh];
      acc[t][0] += zv*w0; acc[t][1] += zv*w1;
    }
  }
  float b0 = bO[tid], b1 = bO[tid+256];
  for (int t=0;t<4;t++){
    out[(tok0+t)*512 + tid      ] = acc[t][0] + b0;
    out[(tok0+t)*512 + tid + 256] = acc[t][1] + b1;
  }
}

// ---------------- launch ----------------
extern "C" void kernel_launch(void* const* d_in, const int* in_sizes, int n_in,
                              void* d_out, int out_size){
  const float* x  = (const float*)d_in[0];
  const float* wA = (const float*)d_in[1];
  const float* wB = (const float*)d_in[2];
  const float* wC = (const float*)d_in[3];
  const float* wD = (const float*)d_in[4];
  const float* wE = (const float*)d_in[5];
  const float* WK = (const float*)d_in[6];
  const float* WV = (const float*)d_in[7];
  const float* WO = (const float*)d_in[8];
  const float* bA = (const float*)d_in[9];
  const float* bB = (const float*)d_in[10];
  const float* bC = (const float*)d_in[11];
  const float* bD = (const float*)d_in[12];
  const float* bE = (const float*)d_in[13];
  const float* bO = (const float*)d_in[14];
  float* out = (float*)d_out;

  k_proj<<<dim3(48,40),256>>>(x,wA,wB,wC,wD,wE,bA,bB,bC,bD,bE);
  k_bsum<<<(B_*T_*DH+255)/256,256>>>();
  k_wkT<<<(NH*DH*4096+255)/256,256>>>(WK);
  size_t s1smem = 24576*sizeof(float);            // 96KB
  cudaFuncSetAttribute(k_step1, cudaFuncAttributeMaxDynamicSharedMemorySize, (int)s1smem);
  k_step1<<<dim3(24,16),256,s1smem>>>();
  size_t s2smem = (2048 + 192*65)*sizeof(float);
  cudaFuncSetAttribute(k_step2, cudaFuncAttributeMaxDynamicSharedMemorySize, (int)s2smem);
  k_step2<<<dim3(384,2),256,s2smem>>>();
  k_dv<<<dim3(48,2,16),256>>>(WV);
  size_t msmem = 56856*sizeof(float);             // ~222KB (R3-proven)
  cudaFuncSetAttribute(k_main, cudaFuncAttributeMaxDynamicSharedMemorySize, (int)msmem);
  k_main<<<dim3(96,NH,B_),384,msmem>>>();
  k_out<<<96,256>>>(WO,bO,out);
}